// round 1
// baseline (speedup 1.0000x reference)
#include <cuda_runtime.h>
#include <cuda_bf16.h>

// GCN 2-layer: out = GCN(relu(GCN(x, W1,b1)), W2,b2)
// Factorization: g[i] = (x W)[i] * dinv[i];  out[d] = dinv[d]*(sum_{e: dst=d} g[src_e] + g[d]) + b
#define NN 100000
#define NE 3200000
#define C0 13
#define C1 32
#define C2 16

__device__ int   g_edges[2 * NE];     // [0..E) = src, [E..2E) = dst (int32)
__device__ int   g_deg[NN];
__device__ float g_dinv[NN];
__device__ float g_g1[NN * C1];
__device__ float g_acc1[NN * C1];
__device__ float g_g2[NN * C2];
__device__ float g_acc2[NN * C2];
__device__ int   g_odd_nonzero;

// ---------------- zero scratch ----------------
__global__ void k_zero() {
    int i = blockIdx.x * blockDim.x + threadIdx.x;   // covers NN*C1
    if (i < NN * C1) g_acc1[i] = 0.0f;
    if (i < NN * C2) g_acc2[i] = 0.0f;
    if (i < NN)      g_deg[i]  = 0;
    if (i == 0)      g_odd_nonzero = 0;
}

// ---------------- detect int64 vs int32 edge_index ----------------
// If int64 (values < 2^31, nonneg), every odd 32-bit word is 0.
__global__ void k_detect(const unsigned* __restrict__ p, int E) {
    int pairs = E < 2048 ? E : 2048;
    int any = 0;
    for (int i = threadIdx.x; i < pairs; i += blockDim.x)
        if (p[2 * i + 1] != 0u) any = 1;
    if (any) atomicOr(&g_odd_nonzero, 1);
}

// ---------------- convert edge_index to int32 ----------------
__global__ void k_convert(const void* __restrict__ p, int twoE) {
    int i = blockIdx.x * blockDim.x + threadIdx.x;
    if (i >= twoE) return;
    int is64 = (g_odd_nonzero == 0);
    int v;
    if (is64) v = (int)((const long long*)p)[i];
    else      v = ((const int*)p)[i];
    g_edges[i] = v;
}

// ---------------- degree (over dst) ----------------
__global__ void k_degree(int E) {
    int e = blockIdx.x * blockDim.x + threadIdx.x;
    if (e < E) atomicAdd(&g_deg[g_edges[E + e]], 1);
}

__global__ void k_dinv(int n) {
    int i = blockIdx.x * blockDim.x + threadIdx.x;
    if (i < n) g_dinv[i] = rsqrtf((float)(g_deg[i] + 1));  // +1 self loop
}

// ---------------- layer1 GEMM: g1[i][c] = (sum_k x[i,k] W1[k,c]) * dinv[i] ----------------
__global__ void k_gemm1(const float* __restrict__ x, const float* __restrict__ W1, int n) {
    __shared__ float sW1[C0 * C1];
    for (int i = threadIdx.x; i < C0 * C1; i += blockDim.x) sW1[i] = W1[i];
    __syncthreads();
    int warp = threadIdx.x >> 5, lane = threadIdx.x & 31;
    int node = blockIdx.x * (blockDim.x >> 5) + warp;
    if (node >= n) return;
    float acc = 0.0f;
    const float* xr = x + (long long)node * C0;
    #pragma unroll
    for (int k = 0; k < C0; k++) acc = fmaf(xr[k], sW1[k * C1 + lane], acc);
    g_g1[node * C1 + lane] = acc * g_dinv[node];
}

// ---------------- scatter layer1: warp per edge ----------------
__global__ void k_scatter1(int E) {
    int t = blockIdx.x * blockDim.x + threadIdx.x;
    int e = t >> 5;
    if (e >= E) return;
    int c = t & 31;
    int s = g_edges[e];
    int d = g_edges[E + e];
    atomicAdd(&g_acc1[d * C1 + c], g_g1[s * C1 + c]);
}

// ---------------- finalize1 + GEMM2 fused (warp per node) ----------------
__global__ void k_fin1_gemm2(const float* __restrict__ W2, const float* __restrict__ b1, int n) {
    __shared__ float sW2[C1 * C2];          // 512
    __shared__ float sh[8 * C1];            // 8 warps * 32 channels
    for (int i = threadIdx.x; i < C1 * C2; i += blockDim.x) sW2[i] = W2[i];
    __syncthreads();
    int warp = threadIdx.x >> 5, lane = threadIdx.x & 31;
    int node = blockIdx.x * 8 + warp;
    if (node >= n) return;
    float di = g_dinv[node];
    float v = g_acc1[node * C1 + lane] + g_g1[node * C1 + lane];
    float h = fmaxf(di * v + b1[lane], 0.0f);
    sh[warp * C1 + lane] = h;
    __syncwarp();
    if (lane < C2) {
        float s = 0.0f;
        #pragma unroll
        for (int c = 0; c < C1; c++) s = fmaf(sh[warp * C1 + c], sW2[c * C2 + lane], s);
        g_g2[node * C2 + lane] = s * di;
    }
}

// ---------------- scatter layer2: half-warp per edge ----------------
__global__ void k_scatter2(int E) {
    int t = blockIdx.x * blockDim.x + threadIdx.x;
    int e = t >> 4;
    if (e >= E) return;
    int c = t & 15;
    int s = g_edges[e];
    int d = g_edges[E + e];
    atomicAdd(&g_acc2[d * C2 + c], g_g2[s * C2 + c]);
}

// ---------------- finalize2 ----------------
__global__ void k_fin2(float* __restrict__ out, const float* __restrict__ b2, int n) {
    int i = blockIdx.x * blockDim.x + threadIdx.x;
    if (i >= n * C2) return;
    int d = i >> 4, c = i & 15;
    out[i] = g_dinv[d] * (g_acc2[i] + g_g2[i]) + b2[c];
}

extern "C" void kernel_launch(void* const* d_in, const int* in_sizes, int n_in,
                              void* d_out, int out_size) {
    const float* x  = (const float*)d_in[0];
    const void*  ei = d_in[1];
    const float* W1 = (const float*)d_in[2];
    const float* b1 = (const float*)d_in[3];
    const float* W2 = (const float*)d_in[4];
    const float* b2 = (const float*)d_in[5];
    float* out = (float*)d_out;

    int n = in_sizes[0] / C0; if (n > NN) n = NN;
    int E = in_sizes[1] / 2;  if (E > NE) E = NE;

    k_zero<<<(NN * C1 + 255) / 256, 256>>>();
    k_detect<<<1, 256>>>((const unsigned*)ei, E);
    k_convert<<<(2 * E + 255) / 256, 256>>>(ei, 2 * E);
    k_degree<<<(E + 255) / 256, 256>>>(E);
    k_dinv<<<(n + 255) / 256, 256>>>(n);
    k_gemm1<<<(n + 7) / 8, 256>>>(x, W1, n);
    long long t1 = (long long)E * 32;
    k_scatter1<<<(unsigned)((t1 + 255) / 256), 256>>>(E);
    k_fin1_gemm2<<<(n + 7) / 8, 256>>>(W2, b1, n);
    long long t2 = (long long)E * 16;
    k_scatter2<<<(unsigned)((t2 + 255) / 256), 256>>>(E);
    k_fin2<<<(n * C2 + 255) / 256, 256>>>(out, b2, n);
}

// round 2
// speedup vs baseline: 2.3175x; 2.3175x over previous
#include <cuda_runtime.h>
#include <cuda_bf16.h>

// 2-layer GCN. Factorization: g[i] = (xW)[i]*dinv[i];
// out[d] = dinv[d]*(sum_{e:dst=d} g[src_e] + g[d]) + b
// This round: CSR-by-dst build (histogram+scan+fill) -> gather-reduce, no float atomics.
#define NN 100000
#define NE 3200000
#define C0 13
#define C1 32
#define C2 16
#define SCANB 1024

__device__ int   g_edges[2 * NE];   // [0..E) src, [E..2E) dst
__device__ int   g_csr[NE];         // src ids grouped by dst
__device__ int   g_deg[NN];
__device__ int   g_off[NN];
__device__ int   g_cur[NN];
__device__ int   g_bsum[128];
__device__ int   g_bpre[128];
__device__ float g_dinv[NN];
__device__ float g_g1[NN * C1];
__device__ float g_g2[NN * C2];
__device__ int   g_odd_nonzero;

// ---------------- zero degree ----------------
__global__ void k_zero(int n) {
    int i = blockIdx.x * blockDim.x + threadIdx.x;
    if (i < n) g_deg[i] = 0;
    if (i == 0) g_odd_nonzero = 0;
}

// ---------------- detect int64 vs int32 edge_index ----------------
__global__ void k_detect(const unsigned* __restrict__ p, int E) {
    int pairs = E < 2048 ? E : 2048;
    int any = 0;
    for (int i = threadIdx.x; i < pairs; i += blockDim.x)
        if (p[2 * i + 1] != 0u) any = 1;
    if (any) atomicOr(&g_odd_nonzero, 1);
}

// ---------------- convert to int32 + degree histogram (dst half) ----------------
__global__ void k_convert_deg(const void* __restrict__ p, int E) {
    int i = blockIdx.x * blockDim.x + threadIdx.x;
    if (i >= 2 * E) return;
    int is64 = (g_odd_nonzero == 0);
    int v;
    if (is64) v = (int)((const long long*)p)[i];
    else      v = ((const int*)p)[i];
    g_edges[i] = v;
    if (i >= E) atomicAdd(&g_deg[v], 1);
}

// ---------------- exclusive scan of deg -> off (3 kernels) ----------------
__global__ void k_scanA(int n) {
    __shared__ int wtot[32];
    int i = blockIdx.x * SCANB + threadIdx.x;
    int lane = threadIdx.x & 31, w = threadIdx.x >> 5;
    int v = (i < n) ? g_deg[i] : 0;
    int s = v;
    #pragma unroll
    for (int o = 1; o < 32; o <<= 1) { int t = __shfl_up_sync(~0u, s, o); if (lane >= o) s += t; }
    if (lane == 31) wtot[w] = s;
    __syncthreads();
    if (w == 0) {
        int t = wtot[lane];
        #pragma unroll
        for (int o = 1; o < 32; o <<= 1) { int u = __shfl_up_sync(~0u, t, o); if (lane >= o) t += u; }
        wtot[lane] = t;
    }
    __syncthreads();
    int excl = s - v + (w > 0 ? wtot[w - 1] : 0);
    if (i < n) g_off[i] = excl;
    if (threadIdx.x == SCANB - 1) g_bsum[blockIdx.x] = excl + v;
}

__global__ void k_scanB(int nblk) {
    __shared__ int sh[128];
    int t = threadIdx.x;
    int v0 = (t < nblk) ? g_bsum[t] : 0;
    sh[t] = v0;
    __syncthreads();
    for (int o = 1; o < 128; o <<= 1) {
        int v = (t >= o) ? sh[t - o] : 0;
        __syncthreads();
        sh[t] += v;
        __syncthreads();
    }
    if (t < nblk) g_bpre[t] = sh[t] - v0;   // exclusive prefix of block sums
}

__global__ void k_scanC(int n) {
    int i = blockIdx.x * blockDim.x + threadIdx.x;
    if (i >= n) return;
    int o = g_off[i] + g_bpre[i >> 10];
    g_off[i] = o;
    g_cur[i] = o;
}

// ---------------- fill CSR ----------------
__global__ void k_fill(int E) {
    int e = blockIdx.x * blockDim.x + threadIdx.x;
    if (e >= E) return;
    int s = g_edges[e];
    int d = g_edges[E + e];
    int pos = atomicAdd(&g_cur[d], 1);
    g_csr[pos] = s;
}

// ---------------- dinv ----------------
__global__ void k_dinv(int n) {
    int i = blockIdx.x * blockDim.x + threadIdx.x;
    if (i < n) g_dinv[i] = rsqrtf((float)(g_deg[i] + 1));
}

// ---------------- layer1 GEMM: g1 = (x W1) * dinv ----------------
__global__ void k_gemm1(const float* __restrict__ x, const float* __restrict__ W1, int n) {
    __shared__ float sW1[C0 * C1];
    for (int i = threadIdx.x; i < C0 * C1; i += blockDim.x) sW1[i] = W1[i];
    __syncthreads();
    int warp = threadIdx.x >> 5, lane = threadIdx.x & 31;
    int node = blockIdx.x * (blockDim.x >> 5) + warp;
    if (node >= n) return;
    float acc = 0.0f;
    const float* xr = x + (long long)node * C0;
    #pragma unroll
    for (int k = 0; k < C0; k++) acc = fmaf(xr[k], sW1[k * C1 + lane], acc);
    g_g1[node * C1 + lane] = acc * g_dinv[node];
}

// ---------------- fused: gather1 + relu + gemm2 -> g2 ----------------
__global__ void k_layer1(const float* __restrict__ W2, const float* __restrict__ b1, int n) {
    __shared__ float sW2[C1 * C2];
    __shared__ float sh[8 * C1];
    for (int i = threadIdx.x; i < C1 * C2; i += blockDim.x) sW2[i] = W2[i];
    __syncthreads();
    int warp = threadIdx.x >> 5, lane = threadIdx.x & 31;
    int node = blockIdx.x * 8 + warp;
    if (node >= n) return;
    int beg = g_off[node];
    int end = beg + g_deg[node];
    float acc = g_g1[node * C1 + lane];   // self loop
    int j = beg;
    for (; j + 4 <= end; j += 4) {
        int s0 = g_csr[j], s1 = g_csr[j + 1], s2 = g_csr[j + 2], s3 = g_csr[j + 3];
        float a0 = g_g1[s0 * C1 + lane];
        float a1 = g_g1[s1 * C1 + lane];
        float a2 = g_g1[s2 * C1 + lane];
        float a3 = g_g1[s3 * C1 + lane];
        acc += (a0 + a1) + (a2 + a3);
    }
    for (; j < end; j++) acc += g_g1[g_csr[j] * C1 + lane];
    float di = g_dinv[node];
    float h = fmaxf(fmaf(di, acc, b1[lane]), 0.0f);
    sh[warp * C1 + lane] = h;
    __syncwarp();
    if (lane < C2) {
        float s = 0.0f;
        #pragma unroll
        for (int c = 0; c < C1; c++) s = fmaf(sh[warp * C1 + c], sW2[c * C2 + lane], s);
        g_g2[node * C2 + lane] = s * di;
    }
}

// ---------------- fused: gather2 + bias -> out. Warp per node, 2 edges/iter ----------------
__global__ void k_layer2(float* __restrict__ out, const float* __restrict__ b2, int n) {
    int warp = threadIdx.x >> 5, lane = threadIdx.x & 31;
    int node = blockIdx.x * 8 + warp;
    if (node >= n) return;
    int lane16 = lane & 15, sel = lane >> 4;
    int beg = g_off[node];
    int deg = g_deg[node];
    float acc = (sel == 0) ? g_g2[node * C2 + lane16] : 0.0f;  // self loop once
    int j = 0;
    for (; j + 4 <= deg; j += 4) {
        int sA = g_csr[beg + j + sel];
        int sB = g_csr[beg + j + 2 + sel];
        float aA = g_g2[sA * C2 + lane16];
        float aB = g_g2[sB * C2 + lane16];
        acc += aA + aB;
    }
    for (; j + 2 <= deg; j += 2) {
        int s = g_csr[beg + j + sel];
        acc += g_g2[s * C2 + lane16];
    }
    if (sel == 0 && j < deg) {
        int s = g_csr[beg + j];
        acc += g_g2[s * C2 + lane16];
    }
    acc += __shfl_xor_sync(~0u, acc, 16);
    if (sel == 0) out[node * C2 + lane16] = fmaf(g_dinv[node], acc, b2[lane16]);
}

extern "C" void kernel_launch(void* const* d_in, const int* in_sizes, int n_in,
                              void* d_out, int out_size) {
    const float* x  = (const float*)d_in[0];
    const void*  ei = d_in[1];
    const float* W1 = (const float*)d_in[2];
    const float* b1 = (const float*)d_in[3];
    const float* W2 = (const float*)d_in[4];
    const float* b2 = (const float*)d_in[5];
    float* out = (float*)d_out;

    int n = in_sizes[0] / C0; if (n > NN) n = NN;
    int E = in_sizes[1] / 2;  if (E > NE) E = NE;
    int nblk = (n + SCANB - 1) / SCANB;

    k_zero<<<(n + 255) / 256, 256>>>(n);
    k_detect<<<1, 256>>>((const unsigned*)ei, E);
    k_convert_deg<<<(2 * E + 255) / 256, 256>>>(ei, E);
    k_scanA<<<nblk, SCANB>>>(n);
    k_scanB<<<1, 128>>>(nblk);
    k_scanC<<<(n + 255) / 256, 256>>>(n);
    k_fill<<<(E + 255) / 256, 256>>>(E);
    k_dinv<<<(n + 255) / 256, 256>>>(n);
    k_gemm1<<<(n + 7) / 8, 256>>>(x, W1, n);
    k_layer1<<<(n + 7) / 8, 256>>>(W2, b1, n);
    k_layer2<<<(n + 7) / 8, 256>>>(out, b2, n);
}